// round 15
// baseline (speedup 1.0000x reference)
#include <cuda_runtime.h>
#include <cuda_bf16.h>
#include <cstdint>

// Shapes: batch_x [32,4096,128] -> N=4096 rows x 4096 (I=64 patches, L=64)
//         pred    [32,1024,128] -> N=4096 rows x 1024 (J=16 patches, L=64)
//
// Math (sum_l q_jl = 1 => lse_i cancels in softmax over j):
//   dot_ij = q_j . x_i (raw x);  u_ij = ne_j - dot_ij  (ne_j = sum q log q)
//   loss = mean_n [ sum_i ( sum_j softmax_j(u_ij)*u_ij + lse_i ) ]
//
// Tensor-core (m16n8k8 tf32) + depth-2 software pipeline: TRIPLE-buffered
// (x, pred) stages in dynamic smem; each CTA keeps 2 rows of DRAM traffic
// in flight at all times. Compute identical to the validated R14 path.
#define NROWS 4096
#define SEQ   4096
#define PREDL 1024
#define ITERS 4
#define NCTAS (NROWS / ITERS)   // 1024
#define XSTR  68
#define QSTR  68
#define XBUF  (64 * XSTR)       // 4352 floats
#define STAGE_F (XBUF + PREDL)  // floats per pipeline stage (21504 B)

__device__ float g_blk_sum[NCTAS];
__device__ unsigned g_ctr = 0;

__device__ __forceinline__ void mma_tf32(float d[4],
                                         uint32_t a0, uint32_t a1,
                                         uint32_t a2, uint32_t a3,
                                         uint32_t b0, uint32_t b1) {
    asm volatile(
        "mma.sync.aligned.m16n8k8.row.col.f32.tf32.tf32.f32 "
        "{%0,%1,%2,%3}, {%4,%5,%6,%7}, {%8,%9}, {%0,%1,%2,%3};"
        : "+f"(d[0]), "+f"(d[1]), "+f"(d[2]), "+f"(d[3])
        : "r"(a0), "r"(a1), "r"(a2), "r"(a3), "r"(b0), "r"(b1));
}

__device__ __forceinline__ void cp_async16(uint32_t smem_addr, const void* gptr) {
    asm volatile("cp.async.ca.shared.global [%0], [%1], 16;"
                 :: "r"(smem_addr), "l"(gptr));
}

__device__ __forceinline__ void prefetch_row(const float* __restrict__ x,
                                             const float* __restrict__ pred,
                                             int n, float* xbuf, float* pbuf,
                                             int t) {
    const float4* x4 = (const float4*)(x + (size_t)n * SEQ);
    #pragma unroll
    for (int k = 0; k < 8; k++) {
        const int idx = t + 128 * k;
        uint32_t dst = (uint32_t)__cvta_generic_to_shared(
            (float4*)(xbuf + (idx >> 4) * XSTR) + (idx & 15));
        cp_async16(dst, x4 + idx);
    }
    const float4* p4 = (const float4*)(pred + (size_t)n * PREDL);
    #pragma unroll
    for (int k = 0; k < 2; k++) {
        const int idx = t + 128 * k;
        uint32_t dst = (uint32_t)__cvta_generic_to_shared((float4*)pbuf + idx);
        cp_async16(dst, p4 + idx);
    }
    asm volatile("cp.async.commit_group;" ::: "memory");
}

extern __shared__ float dyn_smem[];   // 3 stages of (x + pred)

__global__ __launch_bounds__(128, 3)
void kl_fused_kernel(const float* __restrict__ x, const float* __restrict__ pred,
                     float* __restrict__ out) {
    __shared__ __align__(16) float qs[16 * QSTR];
    __shared__ __align__(16) float ne_s[16];
    __shared__ float red[4];
    __shared__ int   is_last_sh;

    const int t    = threadIdx.x;
    const int warp = t >> 5;
    const int lane = t & 31;
    const int n0   = blockIdx.x * ITERS;

    const int gid  = lane >> 2;
    const int tid4 = lane & 3;
    const int mb   = 16 * warp;

    float loss_acc = 0.f;

    // ---- prologue: prefetch rows 0 and 1 (one commit group each) ----
    prefetch_row(x, pred, n0 + 0, dyn_smem + 0 * STAGE_F,
                 dyn_smem + 0 * STAGE_F + XBUF, t);
    prefetch_row(x, pred, n0 + 1, dyn_smem + 1 * STAGE_F,
                 dyn_smem + 1 * STAGE_F + XBUF, t);

    #pragma unroll
    for (int it = 0; it < ITERS; it++) {
        const int buf = it % 3;
        float* xb = dyn_smem + buf * STAGE_F;
        float* pb = xb + XBUF;

        if (it + 2 < ITERS) {
            const int s2 = (it + 2) % 3;
            prefetch_row(x, pred, n0 + it + 2, dyn_smem + s2 * STAGE_F,
                         dyn_smem + s2 * STAGE_F + XBUF, t);
        }
        const int rem = ITERS - 1 - it;   // groups allowed to stay pending
        if (rem >= 2)      asm volatile("cp.async.wait_group 2;" ::: "memory");
        else if (rem == 1) asm volatile("cp.async.wait_group 1;" ::: "memory");
        else               asm volatile("cp.async.wait_group 0;" ::: "memory");
        __syncthreads();   // row it staged

        // ---- Phase B: pb -> q smem [j][68] + ne_j ----
        {
            const float4* pr4 = (const float4*)pb;
            #pragma unroll
            for (int k = 0; k < 2; k++) {
                const int idx = t + 128 * k;
                float4 v = pr4[idx];
                const int j = idx >> 4;
                // naive expsum (inputs ~N(0,1), fp32-safe; validated)
                float e0 = __expf(v.x), e1 = __expf(v.y);
                float e2 = __expf(v.z), e3 = __expf(v.w);
                float E = e0 + e1 + e2 + e3;
                float S = e0 * v.x + e1 * v.y + e2 * v.z + e3 * v.w;
                #pragma unroll
                for (int o = 8; o; o >>= 1) {
                    E += __shfl_xor_sync(0xffffffffu, E, o);
                    S += __shfl_xor_sync(0xffffffffu, S, o);
                }
                float rinv = __frcp_rn(E);
                ((float4*)(qs + j * QSTR))[idx & 15] =
                    make_float4(e0 * rinv, e1 * rinv, e2 * rinv, e3 * rinv);
                if ((lane & 15) == 0) ne_s[j] = S * rinv - __logf(E);
            }
        }
        __syncthreads();   // qs/ne ready

        // ---- Phase C: tensor-core GEMM (warp covers patches mb..mb+15) ----
        const uint32_t* xu = (const uint32_t*)xb;
        const uint32_t* qu = (const uint32_t*)qs;

        float d[2][4];
        #pragma unroll
        for (int nt = 0; nt < 2; nt++)
            #pragma unroll
            for (int rg = 0; rg < 4; rg++) d[nt][rg] = 0.f;

        #pragma unroll
        for (int kt = 0; kt < 8; kt++) {
            const int c = 8 * kt + tid4;
            uint32_t b00 = qu[gid * QSTR + c];
            uint32_t b01 = qu[gid * QSTR + c + 4];
            uint32_t b10 = qu[(8 + gid) * QSTR + c];
            uint32_t b11 = qu[(8 + gid) * QSTR + c + 4];
            const int rowb = (mb + gid) * XSTR;
            uint32_t a0 = xu[rowb + c];
            uint32_t a1 = xu[rowb + 8 * XSTR + c];
            uint32_t a2 = xu[rowb + c + 4];
            uint32_t a3 = xu[rowb + 8 * XSTR + c + 4];
            mma_tf32(d[0], a0, a1, a2, a3, b00, b01);
            mma_tf32(d[1], a0, a1, a2, a3, b10, b11);
        }

        // ---- softmax over j per patch row ----
        const float ne0 = ne_s[2 * tid4];
        const float ne1 = ne_s[2 * tid4 + 1];
        const float ne2 = ne_s[8 + 2 * tid4];
        const float ne3 = ne_s[8 + 2 * tid4 + 1];
        float csum = 0.f;
        #pragma unroll
        for (int half = 0; half < 2; half++) {
            float u0 = ne0 - d[0][2 * half + 0];
            float u1 = ne1 - d[0][2 * half + 1];
            float u2 = ne2 - d[1][2 * half + 0];
            float u3 = ne3 - d[1][2 * half + 1];
            float mx = fmaxf(fmaxf(u0, u1), fmaxf(u2, u3));
            mx = fmaxf(mx, __shfl_xor_sync(0xffffffffu, mx, 1));
            mx = fmaxf(mx, __shfl_xor_sync(0xffffffffu, mx, 2));
            float e0 = __expf(u0 - mx), e1 = __expf(u1 - mx);
            float e2 = __expf(u2 - mx), e3 = __expf(u3 - mx);
            float E  = e0 + e1 + e2 + e3;
            float EU = e0 * u0 + e1 * u1 + e2 * u2 + e3 * u3;
            E  += __shfl_xor_sync(0xffffffffu, E, 1);
            EU += __shfl_xor_sync(0xffffffffu, EU, 1);
            E  += __shfl_xor_sync(0xffffffffu, E, 2);
            EU += __shfl_xor_sync(0xffffffffu, EU, 2);
            if (tid4 == 0) csum += __fdividef(EU, E);
        }

        // ---- lse: 2 lanes per patch (p = t>>1, half = t&1), exact f32 ----
        float Ep = 0.f;
        {
            const int p  = t >> 1;
            const int hc = 8 * (t & 1);
            const float4* xp4 = (const float4*)(xb + p * XSTR) + hc;
            #pragma unroll
            for (int c = 0; c < 8; c++) {
                float4 v = xp4[c];
                Ep += __expf(v.x) + __expf(v.y) + __expf(v.z) + __expf(v.w);
            }
        }
        Ep += __shfl_xor_sync(0xffffffffu, Ep, 1);
        float my = csum;
        if ((t & 1) == 0) my += __logf(Ep);
        loss_acc += my;

        __syncthreads();   // row it fully consumed; stage may be reused
    }

    // ---- reductions: warp -> CTA -> grid (deterministic) ----
    float my = loss_acc;
    #pragma unroll
    for (int o = 16; o; o >>= 1) my += __shfl_xor_sync(0xffffffffu, my, o);
    if (lane == 0) red[warp] = my;
    __syncthreads();
    if (t == 0) {
        g_blk_sum[blockIdx.x] = (red[0] + red[1]) + (red[2] + red[3]);
        __threadfence();
        unsigned prev = atomicAdd(&g_ctr, 1u);
        is_last_sh = (prev == NCTAS - 1);
    }
    __syncthreads();

    if (is_last_sh) {
        float s = 0.f;
        #pragma unroll 4
        for (int i = t; i < NCTAS; i += 128) s += g_blk_sum[i];
        #pragma unroll
        for (int o = 16; o; o >>= 1) s += __shfl_xor_sync(0xffffffffu, s, o);
        if (lane == 0) red[warp] = s;
        __syncthreads();
        if (t == 0) {
            out[0] = ((red[0] + red[1]) + (red[2] + red[3])) * (1.0f / (float)NROWS);
            g_ctr = 0;
        }
    }
}

extern "C" void kernel_launch(void* const* d_in, const int* in_sizes, int n_in,
                              void* d_out, int out_size) {
    const float* x = nullptr;
    const float* pred = nullptr;
    for (int i = 0; i < n_in; i++) {
        if (in_sizes[i] == 32 * 4096 * 128)      x    = (const float*)d_in[i];
        else if (in_sizes[i] == 32 * 1024 * 128) pred = (const float*)d_in[i];
    }
    const int dyn_bytes = 3 * STAGE_F * (int)sizeof(float);   // 64.5KB
    cudaFuncSetAttribute(kl_fused_kernel,
                         cudaFuncAttributeMaxDynamicSharedMemorySize, dyn_bytes);
    kl_fused_kernel<<<NCTAS, 128, dyn_bytes>>>(x, pred, (float*)d_out);
}

// round 16
// speedup vs baseline: 1.0659x; 1.0659x over previous
#include <cuda_runtime.h>
#include <cuda_bf16.h>
#include <cstdint>

// Shapes: batch_x [32,4096,128] -> N=4096 rows x 4096 (I=64 patches, L=64)
//         pred    [32,1024,128] -> N=4096 rows x 1024 (J=16 patches, L=64)
//
// Math (sum_l q_jl = 1 => lse_i cancels in softmax over j):
//   dot_ij = q_j . x_i (raw x);  u_ij = ne_j - dot_ij  (ne_j = sum q log q)
//   loss = mean_n [ sum_i ( sum_j softmax_j(u_ij)*u_ij + lse_i ) ]
//
// Tensor-core (m16n8k8 tf32) + double-buffered row pipeline at 5 CTAs/SM.
// x and q stored TIGHT (64 words/row) with XOR swizzle at float4 granularity:
//   stored_word(row, w) = w ^ ((row & 15) << 2)
// which makes MMA A/B fragment loads and phase stores bank-conflict-free
// while cutting the stage to 20KB (x 16KB + raw pred 4KB).
#define NROWS 4096
#define SEQ   4096
#define PREDL 1024
#define ITERS 4
#define NCTAS (NROWS / ITERS)   // 1024
#define XWORDS (64 * 64)        // tight x row: 4096 floats = 16KB
#define STAGE_F (XWORDS + PREDL)  // 5120 floats = 20KB per stage

__device__ float g_blk_sum[NCTAS];
__device__ unsigned g_ctr = 0;

__device__ __forceinline__ void mma_tf32(float d[4],
                                         uint32_t a0, uint32_t a1,
                                         uint32_t a2, uint32_t a3,
                                         uint32_t b0, uint32_t b1) {
    asm volatile(
        "mma.sync.aligned.m16n8k8.row.col.f32.tf32.tf32.f32 "
        "{%0,%1,%2,%3}, {%4,%5,%6,%7}, {%8,%9}, {%0,%1,%2,%3};"
        : "+f"(d[0]), "+f"(d[1]), "+f"(d[2]), "+f"(d[3])
        : "r"(a0), "r"(a1), "r"(a2), "r"(a3), "r"(b0), "r"(b1));
}

__device__ __forceinline__ void cp_async16(uint32_t smem_addr, const void* gptr) {
    asm volatile("cp.async.ca.shared.global [%0], [%1], 16;"
                 :: "r"(smem_addr), "l"(gptr));
}

// prefetch one row (x swizzled + raw pred) into a stage; one commit group
__device__ __forceinline__ void prefetch_row(const float* __restrict__ x,
                                             const float* __restrict__ pred,
                                             int n, float* xbuf, float* pbuf,
                                             int t) {
    const float4* x4 = (const float4*)(x + (size_t)n * SEQ);
    #pragma unroll
    for (int k = 0; k < 8; k++) {
        const int idx   = t + 128 * k;          // float4 index 0..1023
        const int patch = idx >> 4;
        const int chk   = (idx & 15) ^ (patch & 15);
        uint32_t dst = (uint32_t)__cvta_generic_to_shared(
            (float4*)xbuf + patch * 16 + chk);
        cp_async16(dst, x4 + idx);
    }
    const float4* p4 = (const float4*)(pred + (size_t)n * PREDL);
    #pragma unroll
    for (int k = 0; k < 2; k++) {
        const int idx = t + 128 * k;
        uint32_t dst = (uint32_t)__cvta_generic_to_shared((float4*)pbuf + idx);
        cp_async16(dst, p4 + idx);
    }
    asm volatile("cp.async.commit_group;" ::: "memory");
}

extern __shared__ float dyn_smem[];   // 2 stages of (x + pred) = 40KB

__global__ __launch_bounds__(128, 5)
void kl_fused_kernel(const float* __restrict__ x, const float* __restrict__ pred,
                     float* __restrict__ out) {
    __shared__ __align__(16) float qs[16 * 64];   // tight, swizzled (4KB)
    __shared__ __align__(16) float ne_s[16];
    __shared__ float red[4];
    __shared__ int   is_last_sh;

    const int t    = threadIdx.x;
    const int warp = t >> 5;
    const int lane = t & 31;
    const int n0   = blockIdx.x * ITERS;

    const int gid  = lane >> 2;
    const int tid4 = lane & 3;
    const int mb   = 16 * warp;              // warp's m-tile base (mult of 16)

    float loss_acc = 0.f;

    // ---- prologue: prefetch row 0 ----
    prefetch_row(x, pred, n0, dyn_smem, dyn_smem + XWORDS, t);

    #pragma unroll
    for (int it = 0; it < ITERS; it++) {
        float* xb = dyn_smem + (it & 1) * STAGE_F;
        float* pb = xb + XWORDS;

        if (it + 1 < ITERS) {
            float* xb2 = dyn_smem + ((it + 1) & 1) * STAGE_F;
            prefetch_row(x, pred, n0 + it + 1, xb2, xb2 + XWORDS, t);
            asm volatile("cp.async.wait_group 1;" ::: "memory");
        } else {
            asm volatile("cp.async.wait_group 0;" ::: "memory");
        }
        __syncthreads();   // row it staged

        // ---- Phase B: pb -> q smem (swizzled [j][64]) + ne_j ----
        {
            const float4* pr4 = (const float4*)pb;
            #pragma unroll
            for (int k = 0; k < 2; k++) {
                const int idx = t + 128 * k;
                float4 v = pr4[idx];
                const int j = idx >> 4;
                // naive expsum (inputs ~N(0,1), fp32-safe; validated)
                float e0 = __expf(v.x), e1 = __expf(v.y);
                float e2 = __expf(v.z), e3 = __expf(v.w);
                float E = e0 + e1 + e2 + e3;
                float S = e0 * v.x + e1 * v.y + e2 * v.z + e3 * v.w;
                #pragma unroll
                for (int o = 8; o; o >>= 1) {
                    E += __shfl_xor_sync(0xffffffffu, E, o);
                    S += __shfl_xor_sync(0xffffffffu, S, o);
                }
                float rinv = __frcp_rn(E);
                ((float4*)qs)[j * 16 + ((idx & 15) ^ j)] =
                    make_float4(e0 * rinv, e1 * rinv, e2 * rinv, e3 * rinv);
                if ((lane & 15) == 0) ne_s[j] = S * rinv - __logf(E);
            }
        }
        __syncthreads();   // qs/ne ready

        // ---- Phase C: tensor-core GEMM (warp covers patches mb..mb+15) ----
        const uint32_t* xu = (const uint32_t*)xb;
        const uint32_t* qu = (const uint32_t*)qs;

        float d[2][4];
        #pragma unroll
        for (int nt = 0; nt < 2; nt++)
            #pragma unroll
            for (int rg = 0; rg < 4; rg++) d[nt][rg] = 0.f;

        const int keyA0 = gid << 2;          // (p&15)<<2 for p = mb+gid
        const int keyA1 = (gid + 8) << 2;    // for p = mb+gid+8
        const int keyB0 = gid << 2;          // j = gid
        const int keyB1 = (gid + 8) << 2;    // j = gid+8

        #pragma unroll
        for (int kt = 0; kt < 8; kt++) {
            const int c = 8 * kt + tid4;     // word; bit2 == 0
            uint32_t b00 = qu[gid * 64 + (c ^ keyB0)];
            uint32_t b01 = qu[gid * 64 + ((c ^ keyB0) ^ 4)];
            uint32_t b10 = qu[(8 + gid) * 64 + (c ^ keyB1)];
            uint32_t b11 = qu[(8 + gid) * 64 + ((c ^ keyB1) ^ 4)];
            const int r0 = (mb + gid) * 64;
            const int r1 = (mb + gid + 8) * 64;
            uint32_t a0 = xu[r0 + (c ^ keyA0)];
            uint32_t a1 = xu[r1 + (c ^ keyA1)];
            uint32_t a2 = xu[r0 + ((c ^ keyA0) ^ 4)];
            uint32_t a3 = xu[r1 + ((c ^ keyA1) ^ 4)];
            mma_tf32(d[0], a0, a1, a2, a3, b00, b01);
            mma_tf32(d[1], a0, a1, a2, a3, b10, b11);
        }

        // ---- softmax over j per patch row ----
        const float ne0 = ne_s[2 * tid4];
        const float ne1 = ne_s[2 * tid4 + 1];
        const float ne2 = ne_s[8 + 2 * tid4];
        const float ne3 = ne_s[8 + 2 * tid4 + 1];
        float csum = 0.f;
        #pragma unroll
        for (int half = 0; half < 2; half++) {
            float u0 = ne0 - d[0][2 * half + 0];
            float u1 = ne1 - d[0][2 * half + 1];
            float u2 = ne2 - d[1][2 * half + 0];
            float u3 = ne3 - d[1][2 * half + 1];
            float mx = fmaxf(fmaxf(u0, u1), fmaxf(u2, u3));
            mx = fmaxf(mx, __shfl_xor_sync(0xffffffffu, mx, 1));
            mx = fmaxf(mx, __shfl_xor_sync(0xffffffffu, mx, 2));
            float e0 = __expf(u0 - mx), e1 = __expf(u1 - mx);
            float e2 = __expf(u2 - mx), e3 = __expf(u3 - mx);
            float E  = e0 + e1 + e2 + e3;
            float EU = e0 * u0 + e1 * u1 + e2 * u2 + e3 * u3;
            E  += __shfl_xor_sync(0xffffffffu, E, 1);
            EU += __shfl_xor_sync(0xffffffffu, EU, 1);
            E  += __shfl_xor_sync(0xffffffffu, E, 2);
            EU += __shfl_xor_sync(0xffffffffu, EU, 2);
            if (tid4 == 0) csum += __fdividef(EU, E);
        }

        // ---- lse: 2 lanes per patch (p = t>>1), exact f32, swizzled reads ----
        float Ep = 0.f;
        {
            const int p   = t >> 1;
            const int hc  = 8 * (t & 1);
            const int key = p & 15;
            const float4* xp4 = (const float4*)xb + p * 16;
            #pragma unroll
            for (int c = 0; c < 8; c++) {
                float4 v = xp4[(hc + c) ^ key];
                Ep += __expf(v.x) + __expf(v.y) + __expf(v.z) + __expf(v.w);
            }
        }
        Ep += __shfl_xor_sync(0xffffffffu, Ep, 1);
        float my = csum;
        if ((t & 1) == 0) my += __logf(Ep);
        loss_acc += my;

        __syncthreads();   // row it consumed; its stage may be overwritten
    }

    // ---- reductions: warp -> CTA -> grid (deterministic) ----
    float my = loss_acc;
    #pragma unroll
    for (int o = 16; o; o >>= 1) my += __shfl_xor_sync(0xffffffffu, my, o);
    if (lane == 0) red[warp] = my;
    __syncthreads();
    if (t == 0) {
        g_blk_sum[blockIdx.x] = (red[0] + red[1]) + (red[2] + red[3]);
        __threadfence();
        unsigned prev = atomicAdd(&g_ctr, 1u);
        is_last_sh = (prev == NCTAS - 1);
    }
    __syncthreads();

    if (is_last_sh) {
        float s = 0.f;
        #pragma unroll 4
        for (int i = t; i < NCTAS; i += 128) s += g_blk_sum[i];
        #pragma unroll
        for (int o = 16; o; o >>= 1) s += __shfl_xor_sync(0xffffffffu, s, o);
        if (lane == 0) red[warp] = s;
        __syncthreads();
        if (t == 0) {
            out[0] = ((red[0] + red[1]) + (red[2] + red[3])) * (1.0f / (float)NROWS);
            g_ctr = 0;
        }
    }
}

extern "C" void kernel_launch(void* const* d_in, const int* in_sizes, int n_in,
                              void* d_out, int out_size) {
    const float* x = nullptr;
    const float* pred = nullptr;
    for (int i = 0; i < n_in; i++) {
        if (in_sizes[i] == 32 * 4096 * 128)      x    = (const float*)d_in[i];
        else if (in_sizes[i] == 32 * 1024 * 128) pred = (const float*)d_in[i];
    }
    const int dyn_bytes = 2 * STAGE_F * (int)sizeof(float);   // 40KB
    cudaFuncSetAttribute(kl_fused_kernel,
                         cudaFuncAttributeMaxDynamicSharedMemorySize, dyn_bytes);
    kl_fused_kernel<<<NCTAS, 128, dyn_bytes>>>(x, pred, (float*)d_out);
}

// round 17
// speedup vs baseline: 1.2107x; 1.1359x over previous
#include <cuda_runtime.h>
#include <cuda_bf16.h>
#include <cstdint>

// Shapes: batch_x [32,4096,128] -> N=4096 rows x 4096 (I=64 patches, L=64)
//         pred    [32,1024,128] -> N=4096 rows x 1024 (J=16 patches, L=64)
//
// Math (sum_l q_jl = 1 => lse_i cancels in softmax over j):
//   dot_ij = q_j . x_i (raw x);  u_ij = ne_j - dot_ij  (ne_j = sum q log q)
//   loss = mean_n [ sum_i ( sum_j softmax_j(u_ij)*u_ij + lse_i ) ]
//
// Tensor-core (m16n8k8 tf32). ONE row per CTA, grid 4096: cross-row overlap
// comes from CTA-level interleaving (retiring CTAs are replaced by fresh
// ones whose cp.async bursts overlap neighbors' compute) — measured faster
// than every explicit intra-CTA pipeline variant (R14-R16).
// pred and x are staged in separate cp.async commit groups: phase B waits
// only on pred (wait_group 1); phase C waits on x (wait_group 0).
#define NROWS 4096
#define SEQ   4096
#define PREDL 1024
#define XSTR  68
#define QSTR  68

__device__ float g_blk_sum[NROWS];
__device__ unsigned g_ctr = 0;

__device__ __forceinline__ void mma_tf32(float d[4],
                                         uint32_t a0, uint32_t a1,
                                         uint32_t a2, uint32_t a3,
                                         uint32_t b0, uint32_t b1) {
    asm volatile(
        "mma.sync.aligned.m16n8k8.row.col.f32.tf32.tf32.f32 "
        "{%0,%1,%2,%3}, {%4,%5,%6,%7}, {%8,%9}, {%0,%1,%2,%3};"
        : "+f"(d[0]), "+f"(d[1]), "+f"(d[2]), "+f"(d[3])
        : "r"(a0), "r"(a1), "r"(a2), "r"(a3), "r"(b0), "r"(b1));
}

__device__ __forceinline__ void cp_async16(uint32_t smem_addr, const void* gptr) {
    asm volatile("cp.async.ca.shared.global [%0], [%1], 16;"
                 :: "r"(smem_addr), "l"(gptr));
}

__global__ __launch_bounds__(128, 6)
void kl_fused_kernel(const float* __restrict__ x, const float* __restrict__ pred,
                     float* __restrict__ out) {
    __shared__ __align__(16) float xs[64 * XSTR];    // 17.4KB
    __shared__ __align__(16) float praw[PREDL];      // 4KB
    __shared__ __align__(16) float qs[16 * QSTR];    // 4.35KB
    __shared__ __align__(16) float ne_s[16];
    __shared__ float red[4];
    __shared__ int   is_last_sh;

    const int t    = threadIdx.x;
    const int warp = t >> 5;
    const int lane = t & 31;
    const int n    = blockIdx.x;

    const int gid  = lane >> 2;
    const int tid4 = lane & 3;
    const int mb   = 16 * warp;

    // ---- stage pred (group 0), then x (group 1) via cp.async ----
    {
        const float4* p4 = (const float4*)(pred + (size_t)n * PREDL);
        #pragma unroll
        for (int k = 0; k < 2; k++) {
            const int idx = t + 128 * k;
            uint32_t dst = (uint32_t)__cvta_generic_to_shared((float4*)praw + idx);
            cp_async16(dst, p4 + idx);
        }
        asm volatile("cp.async.commit_group;" ::: "memory");
        const float4* x4 = (const float4*)(x + (size_t)n * SEQ);
        #pragma unroll
        for (int k = 0; k < 8; k++) {
            const int idx = t + 128 * k;
            uint32_t dst = (uint32_t)__cvta_generic_to_shared(
                (float4*)(xs + (idx >> 4) * XSTR) + (idx & 15));
            cp_async16(dst, x4 + idx);
        }
        asm volatile("cp.async.commit_group;" ::: "memory");
    }

    // ---- Phase B: praw -> q smem [j][68] + ne_j (x still in flight) ----
    asm volatile("cp.async.wait_group 1;" ::: "memory");
    __syncthreads();
    {
        const float4* pr4 = (const float4*)praw;
        #pragma unroll
        for (int k = 0; k < 2; k++) {
            const int idx = t + 128 * k;
            float4 v = pr4[idx];
            const int j = idx >> 4;
            // naive expsum (inputs ~N(0,1), fp32-safe; validated)
            float e0 = __expf(v.x), e1 = __expf(v.y);
            float e2 = __expf(v.z), e3 = __expf(v.w);
            float E = e0 + e1 + e2 + e3;
            float S = e0 * v.x + e1 * v.y + e2 * v.z + e3 * v.w;
            #pragma unroll
            for (int o = 8; o; o >>= 1) {
                E += __shfl_xor_sync(0xffffffffu, E, o);
                S += __shfl_xor_sync(0xffffffffu, S, o);
            }
            float rinv = __frcp_rn(E);
            ((float4*)(qs + j * QSTR))[idx & 15] =
                make_float4(e0 * rinv, e1 * rinv, e2 * rinv, e3 * rinv);
            if ((lane & 15) == 0) ne_s[j] = S * rinv - __logf(E);
        }
    }
    asm volatile("cp.async.wait_group 0;" ::: "memory");
    __syncthreads();   // qs/ne ready AND x staged

    // ---- Phase C: tensor-core GEMM (warp covers patches mb..mb+15) ----
    const uint32_t* xu = (const uint32_t*)xs;
    const uint32_t* qu = (const uint32_t*)qs;

    float d[2][4];
    #pragma unroll
    for (int nt = 0; nt < 2; nt++)
        #pragma unroll
        for (int rg = 0; rg < 4; rg++) d[nt][rg] = 0.f;

    #pragma unroll
    for (int kt = 0; kt < 8; kt++) {
        const int c = 8 * kt + tid4;
        uint32_t b00 = qu[gid * QSTR + c];
        uint32_t b01 = qu[gid * QSTR + c + 4];
        uint32_t b10 = qu[(8 + gid) * QSTR + c];
        uint32_t b11 = qu[(8 + gid) * QSTR + c + 4];
        const int rowb = (mb + gid) * XSTR;
        uint32_t a0 = xu[rowb + c];
        uint32_t a1 = xu[rowb + 8 * XSTR + c];
        uint32_t a2 = xu[rowb + c + 4];
        uint32_t a3 = xu[rowb + 8 * XSTR + c + 4];
        mma_tf32(d[0], a0, a1, a2, a3, b00, b01);
        mma_tf32(d[1], a0, a1, a2, a3, b10, b11);
    }

    // ---- softmax over j per patch row ----
    const float ne0 = ne_s[2 * tid4];
    const float ne1 = ne_s[2 * tid4 + 1];
    const float ne2 = ne_s[8 + 2 * tid4];
    const float ne3 = ne_s[8 + 2 * tid4 + 1];
    float csum = 0.f;
    #pragma unroll
    for (int half = 0; half < 2; half++) {
        float u0 = ne0 - d[0][2 * half + 0];
        float u1 = ne1 - d[0][2 * half + 1];
        float u2 = ne2 - d[1][2 * half + 0];
        float u3 = ne3 - d[1][2 * half + 1];
        float mx = fmaxf(fmaxf(u0, u1), fmaxf(u2, u3));
        mx = fmaxf(mx, __shfl_xor_sync(0xffffffffu, mx, 1));
        mx = fmaxf(mx, __shfl_xor_sync(0xffffffffu, mx, 2));
        float e0 = __expf(u0 - mx), e1 = __expf(u1 - mx);
        float e2 = __expf(u2 - mx), e3 = __expf(u3 - mx);
        float E  = e0 + e1 + e2 + e3;
        float EU = e0 * u0 + e1 * u1 + e2 * u2 + e3 * u3;
        E  += __shfl_xor_sync(0xffffffffu, E, 1);
        EU += __shfl_xor_sync(0xffffffffu, EU, 1);
        E  += __shfl_xor_sync(0xffffffffu, E, 2);
        EU += __shfl_xor_sync(0xffffffffu, EU, 2);
        if (tid4 == 0) csum += __fdividef(EU, E);
    }

    // ---- lse: 2 lanes per patch (p = t>>1, half = t&1), exact f32 ----
    float Ep = 0.f;
    {
        const int p  = t >> 1;
        const int hc = 8 * (t & 1);
        const float4* xp4 = (const float4*)(xs + p * XSTR) + hc;
        #pragma unroll
        for (int c = 0; c < 8; c++) {
            float4 v = xp4[c];
            Ep += __expf(v.x) + __expf(v.y) + __expf(v.z) + __expf(v.w);
        }
    }
    Ep += __shfl_xor_sync(0xffffffffu, Ep, 1);
    float my = csum;
    if ((t & 1) == 0) my += __logf(Ep);

    // ---- reductions: warp -> CTA -> grid (deterministic) ----
    #pragma unroll
    for (int o = 16; o; o >>= 1) my += __shfl_xor_sync(0xffffffffu, my, o);
    if (lane == 0) red[warp] = my;
    __syncthreads();
    if (t == 0) {
        g_blk_sum[blockIdx.x] = (red[0] + red[1]) + (red[2] + red[3]);
        __threadfence();
        unsigned prev = atomicAdd(&g_ctr, 1u);
        is_last_sh = (prev == NROWS - 1);
    }
    __syncthreads();

    if (is_last_sh) {
        float s = 0.f;
        #pragma unroll 8
        for (int i = t; i < NROWS; i += 128) s += g_blk_sum[i];
        #pragma unroll
        for (int o = 16; o; o >>= 1) s += __shfl_xor_sync(0xffffffffu, s, o);
        if (lane == 0) red[warp] = s;
        __syncthreads();
        if (t == 0) {
            out[0] = ((red[0] + red[1]) + (red[2] + red[3])) * (1.0f / (float)NROWS);
            g_ctr = 0;
        }
    }
}

extern "C" void kernel_launch(void* const* d_in, const int* in_sizes, int n_in,
                              void* d_out, int out_size) {
    const float* x = nullptr;
    const float* pred = nullptr;
    for (int i = 0; i < n_in; i++) {
        if (in_sizes[i] == 32 * 4096 * 128)      x    = (const float*)d_in[i];
        else if (in_sizes[i] == 32 * 1024 * 128) pred = (const float*)d_in[i];
    }
    kl_fused_kernel<<<NROWS, 128>>>(x, pred, (float*)d_out);
}